// round 9
// baseline (speedup 1.0000x reference)
#include <cuda_runtime.h>
#include <cstdint>
#include <math.h>

// Problem constants (Llama-3-8B-like prefill)
#define T_TOK 4096
#define D_MODEL 4096
#define N_Q 32
#define N_KV 8
#define HD 128
#define SEQ 1024
#define BATCH 4

// Scratch (allocation-free rule: __device__ globals)
__device__ float    g_q[T_TOK * N_Q * HD];       // fp32 -> tf32 bits after rope
__device__ float    g_k[T_TOK * N_KV * HD];
__device__ float    g_v[T_TOK * N_KV * HD];      // fp32 -> tf32 bits after conv
__device__ uint32_t g_att[T_TOK * N_Q * HD];     // tf32 bits (written by attn)
__device__ uint32_t g_xtf[T_TOK * D_MODEL];
__device__ uint32_t g_wqtf[D_MODEL * N_Q * HD];  // transposed [N][K]
__device__ uint32_t g_wktf[D_MODEL * N_KV * HD]; // transposed
__device__ uint32_t g_wvtf[D_MODEL * N_KV * HD]; // transposed
__device__ uint32_t g_wotf[N_Q * HD * D_MODEL];  // transposed

__device__ __forceinline__ uint32_t f2tf(float f) {
    uint32_t r; asm("cvt.rna.tf32.f32 %0, %1;" : "=r"(r) : "f"(f)); return r;
}

#define MMA_TF32(d, a, b)                                                     \
    asm volatile(                                                             \
        "mma.sync.aligned.m16n8k8.row.col.f32.tf32.tf32.f32 "                 \
        "{%0,%1,%2,%3}, {%4,%5,%6,%7}, {%8,%9}, {%0,%1,%2,%3};"               \
        : "+f"((d)[0]), "+f"((d)[1]), "+f"((d)[2]), "+f"((d)[3])              \
        : "r"((a)[0]), "r"((a)[1]), "r"((a)[2]), "r"((a)[3]),                 \
          "r"((b)[0]), "r"((b)[1]))

#define CP16(dst, src) \
    asm volatile("cp.async.cg.shared.global [%0], [%1], 16;" :: "r"(dst), "l"(src))
#define CP_COMMIT() asm volatile("cp.async.commit_group;" ::: "memory")

#define LDSM4(r0, r1, r2, r3, addr)                                           \
    asm volatile("ldmatrix.sync.aligned.m8n8.x4.shared.b16 {%0,%1,%2,%3}, [%4];" \
        : "=r"(r0), "=r"(r1), "=r"(r2), "=r"(r3) : "r"(addr))

// ---------------------------------------------------------------------------
// Elementwise fp32 -> tf32-bits conversion (x, v)
// ---------------------------------------------------------------------------
__global__ void conv_tf(const float* in, uint32_t* out, int n4) {
    int i = blockIdx.x * 256 + threadIdx.x;
    if (i < n4) {
        float4 v = ((const float4*)in)[i];
        ((uint4*)out)[i] = make_uint4(f2tf(v.x), f2tf(v.y), f2tf(v.z), f2tf(v.w));
    }
}

// ---------------------------------------------------------------------------
// Transposing conversion: in [R][C] fp32 -> out [C][R] tf32 bits.
// Tiled 32x32 via smem, both sides coalesced. block (32,8), grid (C/32, R/32).
// ---------------------------------------------------------------------------
__global__ void conv_tf_T(const float* __restrict__ in, uint32_t* __restrict__ out,
                          int R, int C) {
    __shared__ uint32_t t[32][33];
    int bx = blockIdx.x * 32;  // col base in [R][C]
    int by = blockIdx.y * 32;  // row base
    int tx = threadIdx.x, ty = threadIdx.y;
#pragma unroll
    for (int i = 0; i < 32; i += 8)
        t[ty + i][tx] = f2tf(in[(size_t)(by + ty + i) * C + bx + tx]);
    __syncthreads();
#pragma unroll
    for (int i = 0; i < 32; i += 8)
        out[(size_t)(bx + ty + i) * R + by + tx] = t[tx][ty + i];
}

// ---------------------------------------------------------------------------
// TF32 mma.sync GEMM, ldmatrix fragment loads.
// C[M,N] = A[M,K] @ W[K,N], with W given TRANSPOSED as WT[N][K] (tf32 bits).
// 128x128 CTA tile, BK=16, 128 thr, 4 warps (2x2), warp tile 64x64.
// SMEM per stage: As[m:128][k:16] + Bs[n:128][k:16], both stride 20 words.
// cp.async 4-stage pipeline, ONE __syncthreads per chunk.
// ---------------------------------------------------------------------------
#define ASTR 20
#define STG (256 * ASTR)   // words per stage = 5120
__global__ __launch_bounds__(128, 2) void gemm_cp(const uint32_t* __restrict__ A,
                                                  const uint32_t* __restrict__ WT,
                                                  float* __restrict__ C,
                                                  int Kdim, int Ndim) {
    extern __shared__ uint32_t sh[];
    const uint32_t shb = (uint32_t)__cvta_generic_to_shared(sh);
    const int tid = threadIdx.x, lane = tid & 31, w = tid >> 5;
    const int g = lane >> 2, tig = lane & 3;
    const int wm = w & 1, wn = w >> 1;
    const int cm0 = blockIdx.y * 128, cn0 = blockIdx.x * 128;
    const int nchunk = Kdim >> 4;

    // ldmatrix per-lane byte offsets (tile idx = lane/8, row-in-tile = lane%8)
    const int ti = lane >> 3, ri = lane & 7;
    const uint32_t offA = (uint32_t)((((ti & 1) * 8 + ri) * ASTR + (ti >> 1) * 4) * 4);
    const uint32_t offB = (uint32_t)((((ti >> 1) * 8 + ri) * ASTR + (ti & 1) * 4) * 4);

    auto load = [&](int c, int s) {
        const uint32_t sb = shb + s * (STG * 4);
#pragma unroll
        for (int i = 0; i < 4; i++) {
            int seg = i * 128 + tid;
            int row = seg >> 2, ks = seg & 3;
            CP16(sb + (row * ASTR + ks * 4) * 4,
                 A + (size_t)(cm0 + row) * Kdim + c * 16 + ks * 4);
        }
        const uint32_t bb = sb + 128 * ASTR * 4;
#pragma unroll
        for (int i = 0; i < 4; i++) {
            int seg = i * 128 + tid;
            int row = seg >> 2, ks = seg & 3;
            CP16(bb + (row * ASTR + ks * 4) * 4,
                 WT + (size_t)(cn0 + row) * Kdim + c * 16 + ks * 4);
        }
    };

    float acc[4][8][4];
#pragma unroll
    for (int i = 0; i < 4; i++)
#pragma unroll
        for (int j = 0; j < 8; j++)
#pragma unroll
            for (int r = 0; r < 4; r++) acc[i][j][r] = 0.0f;

    load(0, 0); CP_COMMIT();
    load(1, 1); CP_COMMIT();
    load(2, 2); CP_COMMIT();

    for (int c = 0; c < nchunk; c++) {
        asm volatile("cp.async.wait_group 2;" ::: "memory");
        __syncthreads();
        if (c + 3 < nchunk) load(c + 3, (c + 3) & 3);
        CP_COMMIT();

        const uint32_t aBase = shb + (c & 3) * (STG * 4);
        const uint32_t bBase = aBase + 128 * ASTR * 4;
#pragma unroll
        for (int h = 0; h < 2; h++) {
            uint32_t afr[4][4], bfr[8][2];
#pragma unroll
            for (int fm = 0; fm < 4; fm++)
                LDSM4(afr[fm][0], afr[fm][1], afr[fm][2], afr[fm][3],
                      aBase + (uint32_t)(((wm * 64 + fm * 16) * ASTR + h * 8) * 4) + offA);
#pragma unroll
            for (int p = 0; p < 4; p++)
                LDSM4(bfr[2 * p][0], bfr[2 * p][1], bfr[2 * p + 1][0], bfr[2 * p + 1][1],
                      bBase + (uint32_t)(((wn * 64 + p * 16) * ASTR + h * 8) * 4) + offB);
#pragma unroll
            for (int fm = 0; fm < 4; fm++)
#pragma unroll
                for (int fn = 0; fn < 8; fn++)
                    MMA_TF32(acc[fm][fn], afr[fm], bfr[fn]);
        }
    }

    // epilogue: warp writes its 64x64 tile (fp32)
    const int m0 = cm0 + wm * 64;
    const int n0 = cn0 + wn * 64;
#pragma unroll
    for (int fm = 0; fm < 4; fm++) {
        int row = m0 + fm * 16 + g;
#pragma unroll
        for (int fn = 0; fn < 8; fn++) {
            int col = n0 + fn * 8 + tig * 2;
            float* cp = C + (size_t)row * Ndim + col;
            *(float2*)cp = make_float2(acc[fm][fn][0], acc[fm][fn][1]);
            *(float2*)(cp + (size_t)8 * Ndim) = make_float2(acc[fm][fn][2], acc[fm][fn][3]);
        }
    }
}

// ---------------------------------------------------------------------------
// RoPE (NeoX half-split) + in-place tf32 conversion. head < N_Q -> q, else k.
// ---------------------------------------------------------------------------
__global__ void rope_kernel(const int* __restrict__ pos) {
    int t = blockIdx.x;
    int head = blockIdx.y;
    int h = threadIdx.x;  // 0..63
    float* buf;
    if (head < N_Q)
        buf = g_q + ((size_t)t * N_Q + head) * HD;
    else
        buf = g_k + ((size_t)t * N_KV + (head - N_Q)) * HD;

    float p = (float)pos[t];
    float f = p * __expf(-((float)h / 64.0f) * 9.210340371976184f);
    float c = cosf(f);
    float s = sinf(f);
    float x1 = buf[h];
    float x2 = buf[h + 64];
    uint32_t* ub = (uint32_t*)buf;
    ub[h] = f2tf(x1 * c - x2 * s);
    ub[h + 64] = f2tf(x2 * c + x1 * s);
}

// ---------------------------------------------------------------------------
// Flash attention (tf32 mma.sync), causal GQA. Inputs tf32 bits. (verified R7)
// ---------------------------------------------------------------------------
#define QPAD 132
#define KP2 132
#define VPAD 136
#define PP2 68
#define BIG_NEG (-3.0e38f)

__global__ __launch_bounds__(256) void attn_mma() {
    extern __shared__ uint32_t sm4[];
    uint32_t* Qs = sm4;                    // [128][QPAD]
    uint32_t* Ks = Qs + 128 * QPAD;        // [64][KP2]
    uint32_t* Vs = Ks + 64 * KP2;          // [64][VPAD]
    uint32_t* Ps = Vs + 64 * VPAD;         // [128][PP2]
    const uint32_t smb = (uint32_t)__cvta_generic_to_shared(sm4);
    const uint32_t QsB = smb;
    const uint32_t KsB = smb + 128 * QPAD * 4;
    const uint32_t VsB = KsB + 64 * KP2 * 4;

    const uint32_t* qsrc = (const uint32_t*)g_q;
    const uint32_t* ksrc = (const uint32_t*)g_k;
    const uint32_t* vsrc = (const uint32_t*)g_v;

    const int mt = blockIdx.x, n = blockIdx.y, b = blockIdx.z;
    const int kvh = n >> 2;
    const int tid = threadIdx.x, lane = tid & 31, w = tid >> 5;
    const int g = lane >> 2, tig = lane & 3;
    const int m0 = mt * 128;
    const int wrow = w * 16;
    const int wr_min = m0 + wrow;

#pragma unroll
    for (int i = 0; i < 16; i++) {
        int seg = i * 256 + tid;
        int row = seg >> 5, ks = seg & 31;
        CP16(QsB + (row * QPAD + ks * 4) * 4,
             qsrc + ((size_t)(b * SEQ + m0 + row) * N_Q + n) * HD + ks * 4);
    }
    CP_COMMIT();

    float m_i0 = BIG_NEG, m_i1 = BIG_NEG;
    float l_i0 = 0.0f, l_i1 = 0.0f;
    float o[16][4];
#pragma unroll
    for (int fn = 0; fn < 16; fn++)
#pragma unroll
        for (int r = 0; r < 4; r++) o[fn][r] = 0.0f;

    const float scale = 0.08838834764831845f;
    const int ntiles = 2 * (mt + 1);

    for (int jt = 0; jt < ntiles; jt++) {
        __syncthreads();
#pragma unroll
        for (int i = 0; i < 8; i++) {
            int seg = i * 256 + tid;
            int row = seg >> 5, ks = seg & 31;
            size_t gof = ((size_t)(b * SEQ + jt * 64 + row) * N_KV + kvh) * HD + ks * 4;
            CP16(KsB + (row * KP2 + ks * 4) * 4, ksrc + gof);
            CP16(VsB + (row * VPAD + ks * 4) * 4, vsrc + gof);
        }
        CP_COMMIT();
        asm volatile("cp.async.wait_group 0;" ::: "memory");
        __syncthreads();

        if (jt * 64 <= wr_min + 15) {
            float s[8][4];
#pragma unroll
            for (int fn = 0; fn < 8; fn++)
#pragma unroll
                for (int r = 0; r < 4; r++) s[fn][r] = 0.0f;

#pragma unroll
            for (int k0 = 0; k0 < 128; k0 += 8) {
                uint32_t a[4];
                const uint32_t* qp = Qs + (wrow + g) * QPAD + k0 + tig;
                a[0] = qp[0]; a[2] = qp[4];
                a[1] = qp[8 * QPAD]; a[3] = qp[8 * QPAD + 4];
#pragma unroll
                for (int fn = 0; fn < 8; fn++) {
                    uint32_t bb[2];
                    const uint32_t* kp = Ks + (fn * 8 + g) * KP2 + k0 + tig;
                    bb[0] = kp[0]; bb[1] = kp[4];
                    MMA_TF32(s[fn], a, bb);
                }
            }

            const int row0 = wr_min + g, row1 = row0 + 8;
            const bool diag = (jt * 64 + 63 > row0);
            float tm0 = BIG_NEG, tm1 = BIG_NEG;
#pragma unroll
            for (int fn = 0; fn < 8; fn++) {
                int colb = jt * 64 + fn * 8 + 2 * tig;
                float v0 = s[fn][0] * scale;
                float v1 = s[fn][1] * scale;
                float v2 = s[fn][2] * scale;
                float v3 = s[fn][3] * scale;
                if (diag) {
                    if (colb > row0) v0 = BIG_NEG;
                    if (colb + 1 > row0) v1 = BIG_NEG;
                    if (colb > row1) v2 = BIG_NEG;
                    if (colb + 1 > row1) v3 = BIG_NEG;
                }
                s[fn][0] = v0; s[fn][1] = v1; s[fn][2] = v2; s[fn][3] = v3;
                tm0 = fmaxf(tm0, fmaxf(v0, v1));
                tm1 = fmaxf(tm1, fmaxf(v2, v3));
            }
            tm0 = fmaxf(tm0, __shfl_xor_sync(0xffffffff, tm0, 1));
            tm0 = fmaxf(tm0, __shfl_xor_sync(0xffffffff, tm0, 2));
            tm1 = fmaxf(tm1, __shfl_xor_sync(0xffffffff, tm1, 1));
            tm1 = fmaxf(tm1, __shfl_xor_sync(0xffffffff, tm1, 2));

            float mn0 = fmaxf(m_i0, tm0), mn1 = fmaxf(m_i1, tm1);
            float corr0 = __expf(m_i0 - mn0), corr1 = __expf(m_i1 - mn1);
            m_i0 = mn0; m_i1 = mn1;

            float ls0 = 0.0f, ls1 = 0.0f;
            uint32_t* pw = Ps + (wrow + g) * PP2 + 2 * tig;
#pragma unroll
            for (int fn = 0; fn < 8; fn++) {
                float p0 = __expf(s[fn][0] - mn0);
                float p1 = __expf(s[fn][1] - mn0);
                float p2 = __expf(s[fn][2] - mn1);
                float p3 = __expf(s[fn][3] - mn1);
                ls0 += p0 + p1;
                ls1 += p2 + p3;
                pw[fn * 8]     = f2tf(p0);
                pw[fn * 8 + 1] = f2tf(p1);
                pw[8 * PP2 + fn * 8]     = f2tf(p2);
                pw[8 * PP2 + fn * 8 + 1] = f2tf(p3);
            }
            ls0 += __shfl_xor_sync(0xffffffff, ls0, 1);
            ls0 += __shfl_xor_sync(0xffffffff, ls0, 2);
            ls1 += __shfl_xor_sync(0xffffffff, ls1, 1);
            ls1 += __shfl_xor_sync(0xffffffff, ls1, 2);
            l_i0 = l_i0 * corr0 + ls0;
            l_i1 = l_i1 * corr1 + ls1;

#pragma unroll
            for (int fn = 0; fn < 16; fn++) {
                o[fn][0] *= corr0; o[fn][1] *= corr0;
                o[fn][2] *= corr1; o[fn][3] *= corr1;
            }

            __syncwarp();

#pragma unroll
            for (int k0 = 0; k0 < 64; k0 += 8) {
                uint32_t a[4];
                const uint32_t* pp = Ps + (wrow + g) * PP2 + k0 + tig;
                a[0] = pp[0]; a[2] = pp[4];
                a[1] = pp[8 * PP2]; a[3] = pp[8 * PP2 + 4];
#pragma unroll
                for (int fn = 0; fn < 16; fn++) {
                    uint32_t bb[2];
                    const uint32_t* vp = Vs + (k0 + tig) * VPAD + fn * 8 + g;
                    bb[0] = vp[0]; bb[1] = vp[4 * VPAD];
                    MMA_TF32(o[fn], a, bb);
                }
            }
            __syncwarp();
        }
    }

    float inv0 = 1.0f / l_i0, inv1 = 1.0f / l_i1;
    uint32_t* op0 = g_att + ((size_t)(b * SEQ + wr_min + g) * N_Q + n) * HD;
    uint32_t* op1 = op0 + (size_t)8 * N_Q * HD;
#pragma unroll
    for (int fn = 0; fn < 16; fn++) {
        int col = fn * 8 + 2 * tig;
        *(uint2*)(op0 + col) = make_uint2(f2tf(o[fn][0] * inv0), f2tf(o[fn][1] * inv0));
        *(uint2*)(op1 + col) = make_uint2(f2tf(o[fn][2] * inv1), f2tf(o[fn][3] * inv1));
    }
}

// ---------------------------------------------------------------------------
// Launch
// ---------------------------------------------------------------------------
extern "C" void kernel_launch(void* const* d_in, const int* in_sizes, int n_in,
                              void* d_out, int out_size) {
    const float* x  = (const float*)d_in[0];
    const int* pos  = (const int*)d_in[1];
    const float* Wq = (const float*)d_in[2];
    const float* Wk = (const float*)d_in[3];
    const float* Wv = (const float*)d_in[4];
    const float* Wo = (const float*)d_in[5];
    float* out = (float*)d_out;
    (void)in_sizes; (void)n_in; (void)out_size;

    float *qp, *kp, *vp;
    uint32_t *ap, *xtf, *wqtf, *wktf, *wvtf, *wotf;
    cudaGetSymbolAddress((void**)&qp, g_q);
    cudaGetSymbolAddress((void**)&kp, g_k);
    cudaGetSymbolAddress((void**)&vp, g_v);
    cudaGetSymbolAddress((void**)&ap, g_att);
    cudaGetSymbolAddress((void**)&xtf, g_xtf);
    cudaGetSymbolAddress((void**)&wqtf, g_wqtf);
    cudaGetSymbolAddress((void**)&wktf, g_wktf);
    cudaGetSymbolAddress((void**)&wvtf, g_wvtf);
    cudaGetSymbolAddress((void**)&wotf, g_wotf);

    // Pre-convert: x plain; weights converted + transposed to [N][K]
    conv_tf<<<T_TOK * D_MODEL / 1024, 256>>>(x, xtf, T_TOK * D_MODEL / 4);
    conv_tf_T<<<dim3((N_Q * HD) / 32, D_MODEL / 32), dim3(32, 8)>>>(Wq, wqtf, D_MODEL, N_Q * HD);
    conv_tf_T<<<dim3((N_KV * HD) / 32, D_MODEL / 32), dim3(32, 8)>>>(Wk, wktf, D_MODEL, N_KV * HD);
    conv_tf_T<<<dim3((N_KV * HD) / 32, D_MODEL / 32), dim3(32, 8)>>>(Wv, wvtf, D_MODEL, N_KV * HD);
    conv_tf_T<<<dim3(D_MODEL / 32, (N_Q * HD) / 32), dim3(32, 8)>>>(Wo, wotf, N_Q * HD, D_MODEL);

    const int gemm_smem = 4 * STG * 4;  // 81920 B
    cudaFuncSetAttribute(gemm_cp, cudaFuncAttributeMaxDynamicSharedMemorySize, gemm_smem);

    // QKV projections
    gemm_cp<<<dim3(32, 32), 128, gemm_smem>>>(xtf, wqtf, qp, D_MODEL, N_Q * HD);
    gemm_cp<<<dim3(8, 32), 128, gemm_smem>>>(xtf, wktf, kp, D_MODEL, N_KV * HD);
    gemm_cp<<<dim3(8, 32), 128, gemm_smem>>>(xtf, wvtf, vp, D_MODEL, N_KV * HD);

    // RoPE (+ in-place tf32 conversion of q,k); v converted in place
    rope_kernel<<<dim3(T_TOK, N_Q + N_KV), 64>>>(pos);
    conv_tf<<<T_TOK * N_KV * HD / 1024, 256>>>(vp, (uint32_t*)vp, T_TOK * N_KV * HD / 4);

    // Flash attention (tensor cores) -> tf32 bits in g_att
    const int attn_smem = (128 * QPAD + 64 * KP2 + 64 * VPAD + 128 * PP2) * 4;
    cudaFuncSetAttribute(attn_mma, cudaFuncAttributeMaxDynamicSharedMemorySize, attn_smem);
    attn_mma<<<dim3(SEQ / 128, N_Q, BATCH), 256, attn_smem>>>();

    // Output projection (fp32 out)
    gemm_cp<<<dim3(32, 32), 128, gemm_smem>>>(ap, wotf, out, D_MODEL, D_MODEL);
}

// round 12
// speedup vs baseline: 1.4169x; 1.4169x over previous
#include <cuda_runtime.h>
#include <cstdint>
#include <math.h>

// Problem constants (Llama-3-8B-like prefill)
#define T_TOK 4096
#define D_MODEL 4096
#define N_Q 32
#define N_KV 8
#define HD 128
#define SEQ 1024
#define BATCH 4

// Scratch (allocation-free rule: __device__ globals)
__device__ float    g_q[T_TOK * N_Q * HD];       // fp32 -> tf32 bits after rope
__device__ float    g_k[T_TOK * N_KV * HD];
__device__ float    g_v[T_TOK * N_KV * HD];      // fp32 -> tf32 bits after conv
__device__ uint32_t g_att[T_TOK * N_Q * HD];     // tf32 bits (written by attn)
__device__ uint32_t g_xtf[T_TOK * D_MODEL];
__device__ uint32_t g_wqtf[D_MODEL * N_Q * HD];
__device__ uint32_t g_wktf[D_MODEL * N_KV * HD];
__device__ uint32_t g_wvtf[D_MODEL * N_KV * HD];
__device__ uint32_t g_wotf[N_Q * HD * D_MODEL];

__device__ __forceinline__ uint32_t f2tf(float f) {
    uint32_t r; asm("cvt.rna.tf32.f32 %0, %1;" : "=r"(r) : "f"(f)); return r;
}

#define MMA_TF32(d, a, b)                                                     \
    asm volatile(                                                             \
        "mma.sync.aligned.m16n8k8.row.col.f32.tf32.tf32.f32 "                 \
        "{%0,%1,%2,%3}, {%4,%5,%6,%7}, {%8,%9}, {%0,%1,%2,%3};"               \
        : "+f"((d)[0]), "+f"((d)[1]), "+f"((d)[2]), "+f"((d)[3])              \
        : "r"((a)[0]), "r"((a)[1]), "r"((a)[2]), "r"((a)[3]),                 \
          "r"((b)[0]), "r"((b)[1]))

#define CP16(dst, src) \
    asm volatile("cp.async.cg.shared.global [%0], [%1], 16;" :: "r"(dst), "l"(src))
#define CP_COMMIT() asm volatile("cp.async.commit_group;" ::: "memory")

#define LDSM4(r0, r1, r2, r3, addr)                                           \
    asm volatile("ldmatrix.sync.aligned.m8n8.x4.shared.b16 {%0,%1,%2,%3}, [%4];" \
        : "=r"(r0), "=r"(r1), "=r"(r2), "=r"(r3) : "r"(addr))

// ---------------------------------------------------------------------------
// Elementwise fp32 -> tf32-bits conversion
// ---------------------------------------------------------------------------
__global__ void conv_tf(const float* in, uint32_t* out, int n4) {
    int i = blockIdx.x * 256 + threadIdx.x;
    if (i < n4) {
        float4 v = ((const float4*)in)[i];
        ((uint4*)out)[i] = make_uint4(f2tf(v.x), f2tf(v.y), f2tf(v.z), f2tf(v.w));
    }
}

// ---------------------------------------------------------------------------
// TF32 mma.sync GEMM on pre-converted u32 operands. (R7 layout: B dense [k][n])
// C[M,N] = A[M,K] @ W[K,N]; 128x128 CTA tile, BK=16, 128 thr, 4 warps (2x2),
// warp tile 64x64. cp.async 4-stage pipeline, ONE __syncthreads per chunk.
// A-fragments via ldmatrix (from [m][k] stride-20); B-fragments scalar LDS.
// ---------------------------------------------------------------------------
#define ASTR 20
#define BSTR 136
#define STG (128 * ASTR + 16 * BSTR)   // words per stage = 4736
__global__ __launch_bounds__(128, 2) void gemm_cp(const uint32_t* __restrict__ A,
                                                  const uint32_t* __restrict__ W,
                                                  float* __restrict__ C,
                                                  int Kdim, int Ndim) {
    extern __shared__ uint32_t sh[];
    const uint32_t shb = (uint32_t)__cvta_generic_to_shared(sh);
    const int tid = threadIdx.x, lane = tid & 31, w = tid >> 5;
    const int g = lane >> 2, tig = lane & 3;
    const int wm = w & 1, wn = w >> 1;
    const int cm0 = blockIdx.y * 128, cn0 = blockIdx.x * 128;
    const int nchunk = Kdim >> 4;

    // ldmatrix per-lane byte offset for A (tile idx = lane/8, row-in-tile = lane%8)
    // tiles: t0=rows0-7,k0-3  t1=rows8-15,k0-3  t2=rows0-7,k4-7  t3=rows8-15,k4-7
    const int ti = lane >> 3, ri = lane & 7;
    const uint32_t offA = (uint32_t)((((ti & 1) * 8 + ri) * ASTR + (ti >> 1) * 4) * 4);

    auto load = [&](int c, int s) {
        const uint32_t sb = shb + s * (STG * 4);
#pragma unroll
        for (int i = 0; i < 4; i++) {
            int seg = i * 128 + tid;
            int row = seg >> 2, ks = seg & 3;
            CP16(sb + (row * ASTR + ks * 4) * 4,
                 A + (size_t)(cm0 + row) * Kdim + c * 16 + ks * 4);
        }
        const uint32_t bb = sb + 128 * ASTR * 4;
#pragma unroll
        for (int i = 0; i < 4; i++) {
            int seg = i * 128 + tid;
            int row = seg >> 5, ns = seg & 31;
            CP16(bb + (row * BSTR + ns * 4) * 4,
                 W + (size_t)(c * 16 + row) * Ndim + cn0 + ns * 4);
        }
    };

    float acc[4][8][4];
#pragma unroll
    for (int i = 0; i < 4; i++)
#pragma unroll
        for (int j = 0; j < 8; j++)
#pragma unroll
            for (int r = 0; r < 4; r++) acc[i][j][r] = 0.0f;

    load(0, 0); CP_COMMIT();
    load(1, 1); CP_COMMIT();
    load(2, 2); CP_COMMIT();

    for (int c = 0; c < nchunk; c++) {
        asm volatile("cp.async.wait_group 2;" ::: "memory");
        __syncthreads();
        if (c + 3 < nchunk) load(c + 3, (c + 3) & 3);
        CP_COMMIT();

        const uint32_t aBase = shb + (c & 3) * (STG * 4);
        const uint32_t* a = sh + (c & 3) * STG;
        const uint32_t* b = a + 128 * ASTR;
#pragma unroll
        for (int h = 0; h < 2; h++) {
            uint32_t afr[4][4], bfr[8][2];
#pragma unroll
            for (int fm = 0; fm < 4; fm++)
                LDSM4(afr[fm][0], afr[fm][1], afr[fm][2], afr[fm][3],
                      aBase + (uint32_t)(((wm * 64 + fm * 16) * ASTR + h * 8) * 4) + offA);
#pragma unroll
            for (int fn = 0; fn < 8; fn++) {
                const uint32_t* p = b + (h * 8 + tig) * BSTR + wn * 64 + fn * 8 + g;
                bfr[fn][0] = p[0];
                bfr[fn][1] = p[4 * BSTR];
            }
#pragma unroll
            for (int fm = 0; fm < 4; fm++)
#pragma unroll
                for (int fn = 0; fn < 8; fn++)
                    MMA_TF32(acc[fm][fn], afr[fm], bfr[fn]);
        }
    }

    // epilogue: warp writes its 64x64 tile (fp32)
    const int m0 = cm0 + wm * 64;
    const int n0 = cn0 + wn * 64;
#pragma unroll
    for (int fm = 0; fm < 4; fm++) {
        int row = m0 + fm * 16 + g;
#pragma unroll
        for (int fn = 0; fn < 8; fn++) {
            int col = n0 + fn * 8 + tig * 2;
            float* cp = C + (size_t)row * Ndim + col;
            *(float2*)cp = make_float2(acc[fm][fn][0], acc[fm][fn][1]);
            *(float2*)(cp + (size_t)8 * Ndim) = make_float2(acc[fm][fn][2], acc[fm][fn][3]);
        }
    }
}

// ---------------------------------------------------------------------------
// RoPE (NeoX half-split) + in-place tf32 conversion. head < N_Q -> q, else k.
// ---------------------------------------------------------------------------
__global__ void rope_kernel(const int* __restrict__ pos) {
    int t = blockIdx.x;
    int head = blockIdx.y;
    int h = threadIdx.x;  // 0..63
    float* buf;
    if (head < N_Q)
        buf = g_q + ((size_t)t * N_Q + head) * HD;
    else
        buf = g_k + ((size_t)t * N_KV + (head - N_Q)) * HD;

    float p = (float)pos[t];
    float f = p * __expf(-((float)h / 64.0f) * 9.210340371976184f);
    float c = cosf(f);
    float s = sinf(f);
    float x1 = buf[h];
    float x2 = buf[h + 64];
    uint32_t* ub = (uint32_t*)buf;
    ub[h] = f2tf(x1 * c - x2 * s);
    ub[h + 64] = f2tf(x2 * c + x1 * s);
}

// ---------------------------------------------------------------------------
// Flash attention (tf32 mma.sync), causal GQA. Inputs tf32 bits. (verified R7)
// ---------------------------------------------------------------------------
#define QPAD 132
#define KP2 132
#define VPAD 136
#define PP2 68
#define BIG_NEG (-3.0e38f)

__global__ __launch_bounds__(256) void attn_mma() {
    extern __shared__ uint32_t sm4[];
    uint32_t* Qs = sm4;                    // [128][QPAD]
    uint32_t* Ks = Qs + 128 * QPAD;        // [64][KP2]
    uint32_t* Vs = Ks + 64 * KP2;          // [64][VPAD]
    uint32_t* Ps = Vs + 64 * VPAD;         // [128][PP2]
    const uint32_t smb = (uint32_t)__cvta_generic_to_shared(sm4);
    const uint32_t QsB = smb;
    const uint32_t KsB = smb + 128 * QPAD * 4;
    const uint32_t VsB = KsB + 64 * KP2 * 4;

    const uint32_t* qsrc = (const uint32_t*)g_q;
    const uint32_t* ksrc = (const uint32_t*)g_k;
    const uint32_t* vsrc = (const uint32_t*)g_v;

    const int mt = blockIdx.x, n = blockIdx.y, b = blockIdx.z;
    const int kvh = n >> 2;
    const int tid = threadIdx.x, lane = tid & 31, w = tid >> 5;
    const int g = lane >> 2, tig = lane & 3;
    const int m0 = mt * 128;
    const int wrow = w * 16;
    const int wr_min = m0 + wrow;

#pragma unroll
    for (int i = 0; i < 16; i++) {
        int seg = i * 256 + tid;
        int row = seg >> 5, ks = seg & 31;
        CP16(QsB + (row * QPAD + ks * 4) * 4,
             qsrc + ((size_t)(b * SEQ + m0 + row) * N_Q + n) * HD + ks * 4);
    }
    CP_COMMIT();

    float m_i0 = BIG_NEG, m_i1 = BIG_NEG;
    float l_i0 = 0.0f, l_i1 = 0.0f;
    float o[16][4];
#pragma unroll
    for (int fn = 0; fn < 16; fn++)
#pragma unroll
        for (int r = 0; r < 4; r++) o[fn][r] = 0.0f;

    const float scale = 0.08838834764831845f;
    const int ntiles = 2 * (mt + 1);

    for (int jt = 0; jt < ntiles; jt++) {
        __syncthreads();
#pragma unroll
        for (int i = 0; i < 8; i++) {
            int seg = i * 256 + tid;
            int row = seg >> 5, ks = seg & 31;
            size_t gof = ((size_t)(b * SEQ + jt * 64 + row) * N_KV + kvh) * HD + ks * 4;
            CP16(KsB + (row * KP2 + ks * 4) * 4, ksrc + gof);
            CP16(VsB + (row * VPAD + ks * 4) * 4, vsrc + gof);
        }
        CP_COMMIT();
        asm volatile("cp.async.wait_group 0;" ::: "memory");
        __syncthreads();

        if (jt * 64 <= wr_min + 15) {
            float s[8][4];
#pragma unroll
            for (int fn = 0; fn < 8; fn++)
#pragma unroll
                for (int r = 0; r < 4; r++) s[fn][r] = 0.0f;

#pragma unroll
            for (int k0 = 0; k0 < 128; k0 += 8) {
                uint32_t a[4];
                const uint32_t* qp = Qs + (wrow + g) * QPAD + k0 + tig;
                a[0] = qp[0]; a[2] = qp[4];
                a[1] = qp[8 * QPAD]; a[3] = qp[8 * QPAD + 4];
#pragma unroll
                for (int fn = 0; fn < 8; fn++) {
                    uint32_t bb[2];
                    const uint32_t* kp = Ks + (fn * 8 + g) * KP2 + k0 + tig;
                    bb[0] = kp[0]; bb[1] = kp[4];
                    MMA_TF32(s[fn], a, bb);
                }
            }

            const int row0 = wr_min + g, row1 = row0 + 8;
            const bool diag = (jt * 64 + 63 > row0);
            float tm0 = BIG_NEG, tm1 = BIG_NEG;
#pragma unroll
            for (int fn = 0; fn < 8; fn++) {
                int colb = jt * 64 + fn * 8 + 2 * tig;
                float v0 = s[fn][0] * scale;
                float v1 = s[fn][1] * scale;
                float v2 = s[fn][2] * scale;
                float v3 = s[fn][3] * scale;
                if (diag) {
                    if (colb > row0) v0 = BIG_NEG;
                    if (colb + 1 > row0) v1 = BIG_NEG;
                    if (colb > row1) v2 = BIG_NEG;
                    if (colb + 1 > row1) v3 = BIG_NEG;
                }
                s[fn][0] = v0; s[fn][1] = v1; s[fn][2] = v2; s[fn][3] = v3;
                tm0 = fmaxf(tm0, fmaxf(v0, v1));
                tm1 = fmaxf(tm1, fmaxf(v2, v3));
            }
            tm0 = fmaxf(tm0, __shfl_xor_sync(0xffffffff, tm0, 1));
            tm0 = fmaxf(tm0, __shfl_xor_sync(0xffffffff, tm0, 2));
            tm1 = fmaxf(tm1, __shfl_xor_sync(0xffffffff, tm1, 1));
            tm1 = fmaxf(tm1, __shfl_xor_sync(0xffffffff, tm1, 2));

            float mn0 = fmaxf(m_i0, tm0), mn1 = fmaxf(m_i1, tm1);
            float corr0 = __expf(m_i0 - mn0), corr1 = __expf(m_i1 - mn1);
            m_i0 = mn0; m_i1 = mn1;

            float ls0 = 0.0f, ls1 = 0.0f;
            uint32_t* pw = Ps + (wrow + g) * PP2 + 2 * tig;
#pragma unroll
            for (int fn = 0; fn < 8; fn++) {
                float p0 = __expf(s[fn][0] - mn0);
                float p1 = __expf(s[fn][1] - mn0);
                float p2 = __expf(s[fn][2] - mn1);
                float p3 = __expf(s[fn][3] - mn1);
                ls0 += p0 + p1;
                ls1 += p2 + p3;
                pw[fn * 8]     = f2tf(p0);
                pw[fn * 8 + 1] = f2tf(p1);
                pw[8 * PP2 + fn * 8]     = f2tf(p2);
                pw[8 * PP2 + fn * 8 + 1] = f2tf(p3);
            }
            ls0 += __shfl_xor_sync(0xffffffff, ls0, 1);
            ls0 += __shfl_xor_sync(0xffffffff, ls0, 2);
            ls1 += __shfl_xor_sync(0xffffffff, ls1, 1);
            ls1 += __shfl_xor_sync(0xffffffff, ls1, 2);
            l_i0 = l_i0 * corr0 + ls0;
            l_i1 = l_i1 * corr1 + ls1;

#pragma unroll
            for (int fn = 0; fn < 16; fn++) {
                o[fn][0] *= corr0; o[fn][1] *= corr0;
                o[fn][2] *= corr1; o[fn][3] *= corr1;
            }

            __syncwarp();

#pragma unroll
            for (int k0 = 0; k0 < 64; k0 += 8) {
                uint32_t a[4];
                const uint32_t* pp = Ps + (wrow + g) * PP2 + k0 + tig;
                a[0] = pp[0]; a[2] = pp[4];
                a[1] = pp[8 * PP2]; a[3] = pp[8 * PP2 + 4];
#pragma unroll
                for (int fn = 0; fn < 16; fn++) {
                    uint32_t bb[2];
                    const uint32_t* vp = Vs + (k0 + tig) * VPAD + fn * 8 + g;
                    bb[0] = vp[0]; bb[1] = vp[4 * VPAD];
                    MMA_TF32(o[fn], a, bb);
                }
            }
            __syncwarp();
        }
    }

    float inv0 = 1.0f / l_i0, inv1 = 1.0f / l_i1;
    uint32_t* op0 = g_att + ((size_t)(b * SEQ + wr_min + g) * N_Q + n) * HD;
    uint32_t* op1 = op0 + (size_t)8 * N_Q * HD;
#pragma unroll
    for (int fn = 0; fn < 16; fn++) {
        int col = fn * 8 + 2 * tig;
        *(uint2*)(op0 + col) = make_uint2(f2tf(o[fn][0] * inv0), f2tf(o[fn][1] * inv0));
        *(uint2*)(op1 + col) = make_uint2(f2tf(o[fn][2] * inv1), f2tf(o[fn][3] * inv1));
    }
}

// ---------------------------------------------------------------------------
// Launch
// ---------------------------------------------------------------------------
extern "C" void kernel_launch(void* const* d_in, const int* in_sizes, int n_in,
                              void* d_out, int out_size) {
    const float* x  = (const float*)d_in[0];
    const int* pos  = (const int*)d_in[1];
    const float* Wq = (const float*)d_in[2];
    const float* Wk = (const float*)d_in[3];
    const float* Wv = (const float*)d_in[4];
    const float* Wo = (const float*)d_in[5];
    float* out = (float*)d_out;
    (void)in_sizes; (void)n_in; (void)out_size;

    float *qp, *kp, *vp;
    uint32_t *ap, *xtf, *wqtf, *wktf, *wvtf, *wotf;
    cudaGetSymbolAddress((void**)&qp, g_q);
    cudaGetSymbolAddress((void**)&kp, g_k);
    cudaGetSymbolAddress((void**)&vp, g_v);
    cudaGetSymbolAddress((void**)&ap, g_att);
    cudaGetSymbolAddress((void**)&xtf, g_xtf);
    cudaGetSymbolAddress((void**)&wqtf, g_wqtf);
    cudaGetSymbolAddress((void**)&wktf, g_wktf);
    cudaGetSymbolAddress((void**)&wvtf, g_wvtf);
    cudaGetSymbolAddress((void**)&wotf, g_wotf);

    // Pre-convert operands to tf32 bits (R7 scheme: no transposes)
    conv_tf<<<T_TOK * D_MODEL / 1024, 256>>>(x, xtf, T_TOK * D_MODEL / 4);
    conv_tf<<<D_MODEL * N_Q * HD / 1024, 256>>>(Wq, wqtf, D_MODEL * N_Q * HD / 4);
    conv_tf<<<D_MODEL * N_KV * HD / 1024, 256>>>(Wk, wktf, D_MODEL * N_KV * HD / 4);
    conv_tf<<<D_MODEL * N_KV * HD / 1024, 256>>>(Wv, wvtf, D_MODEL * N_KV * HD / 4);
    conv_tf<<<N_Q * HD * D_MODEL / 1024, 256>>>(Wo, wotf, N_Q * HD * D_MODEL / 4);

    const int gemm_smem = 4 * STG * 4;  // 75776 B
    cudaFuncSetAttribute(gemm_cp, cudaFuncAttributeMaxDynamicSharedMemorySize, gemm_smem);

    // QKV projections
    gemm_cp<<<dim3(32, 32), 128, gemm_smem>>>(xtf, wqtf, qp, D_MODEL, N_Q * HD);
    gemm_cp<<<dim3(8, 32), 128, gemm_smem>>>(xtf, wktf, kp, D_MODEL, N_KV * HD);
    gemm_cp<<<dim3(8, 32), 128, gemm_smem>>>(xtf, wvtf, vp, D_MODEL, N_KV * HD);

    // RoPE (+ in-place tf32 conversion of q,k); v converted in place
    rope_kernel<<<dim3(T_TOK, N_Q + N_KV), 64>>>(pos);
    conv_tf<<<T_TOK * N_KV * HD / 1024, 256>>>(vp, (uint32_t*)vp, T_TOK * N_KV * HD / 4);

    // Flash attention (tensor cores) -> tf32 bits in g_att
    const int attn_smem = (128 * QPAD + 64 * KP2 + 64 * VPAD + 128 * PP2) * 4;
    cudaFuncSetAttribute(attn_mma, cudaFuncAttributeMaxDynamicSharedMemorySize, attn_smem);
    attn_mma<<<dim3(SEQ / 128, N_Q, BATCH), 256, attn_smem>>>();

    // Output projection (fp32 out)
    gemm_cp<<<dim3(32, 32), 128, gemm_smem>>>(ap, wotf, out, D_MODEL, D_MODEL);
}

// round 13
// speedup vs baseline: 2.7619x; 1.9492x over previous
#include <cuda_runtime.h>
#include <cuda_fp16.h>
#include <cstdint>
#include <math.h>

// Problem constants (Llama-3-8B-like prefill)
#define T_TOK 4096
#define D_MODEL 4096
#define N_Q 32
#define N_KV 8
#define HD 128
#define SEQ 1024
#define BATCH 4

// Scratch (allocation-free rule: __device__ globals), all fp16
__device__ __half g_xh[T_TOK * D_MODEL];
__device__ __half g_wqh[D_MODEL * N_Q * HD];
__device__ __half g_wkh[D_MODEL * N_KV * HD];
__device__ __half g_wvh[D_MODEL * N_KV * HD];
__device__ __half g_woh[N_Q * HD * D_MODEL];
__device__ __half g_qh[T_TOK * N_Q * HD];
__device__ __half g_kh[T_TOK * N_KV * HD];
__device__ __half g_vh[T_TOK * N_KV * HD];
__device__ __half g_atth[T_TOK * N_Q * HD];

__device__ __forceinline__ uint32_t packh2(float a, float b) {
    __half2 h = __floats2half2_rn(a, b);
    return *(uint32_t*)&h;
}

#define MMA_F16(d, a, b)                                                      \
    asm volatile(                                                             \
        "mma.sync.aligned.m16n8k16.row.col.f32.f16.f16.f32 "                  \
        "{%0,%1,%2,%3}, {%4,%5,%6,%7}, {%8,%9}, {%0,%1,%2,%3};"               \
        : "+f"((d)[0]), "+f"((d)[1]), "+f"((d)[2]), "+f"((d)[3])              \
        : "r"((a)[0]), "r"((a)[1]), "r"((a)[2]), "r"((a)[3]),                 \
          "r"((b)[0]), "r"((b)[1]))

#define CP16(dst, src) \
    asm volatile("cp.async.cg.shared.global [%0], [%1], 16;" :: "r"(dst), "l"(src))
#define CP_COMMIT() asm volatile("cp.async.commit_group;" ::: "memory")

#define LDSM4(r0, r1, r2, r3, addr)                                           \
    asm volatile("ldmatrix.sync.aligned.m8n8.x4.shared.b16 {%0,%1,%2,%3}, [%4];" \
        : "=r"(r0), "=r"(r1), "=r"(r2), "=r"(r3) : "r"(addr))
#define LDSM4T(r0, r1, r2, r3, addr)                                          \
    asm volatile("ldmatrix.sync.aligned.m8n8.x4.trans.shared.b16 {%0,%1,%2,%3}, [%4];" \
        : "=r"(r0), "=r"(r1), "=r"(r2), "=r"(r3) : "r"(addr))

// ---------------------------------------------------------------------------
// fp32 -> fp16 conversion, 8 elems/thread
// ---------------------------------------------------------------------------
__global__ void conv_h(const float* __restrict__ in, __half* __restrict__ out, int n8) {
    int i = blockIdx.x * 256 + threadIdx.x;
    if (i < n8) {
        float4 a = ((const float4*)in)[2 * i];
        float4 b = ((const float4*)in)[2 * i + 1];
        uint4 o = make_uint4(packh2(a.x, a.y), packh2(a.z, a.w),
                             packh2(b.x, b.y), packh2(b.z, b.w));
        ((uint4*)out)[i] = o;
    }
}

// ---------------------------------------------------------------------------
// FP16 mma.sync GEMM: C[M,N] = A[M,K] @ W[K,N].
// 128x128 CTA tile, BK=32, 128 thr, 4 warps (2x2), warp tile 64x64.
// All fragments via ldmatrix (A non-trans from [m][k]; W trans from [k][n]).
// SMEM/stage: A [128][40h] + B [32][136h]; 4-stage cp.async, 1 barrier/chunk.
// out_half: write __half (q/k/v) else fp32 (O proj).
// ---------------------------------------------------------------------------
#define AH 40
#define BH 136
#define STGH (128 * AH + 32 * BH)   // 9472 halves = 18944 B
__global__ __launch_bounds__(128, 2) void gemm_h(const __half* __restrict__ A,
                                                 const __half* __restrict__ W,
                                                 void* __restrict__ Cout,
                                                 int Kdim, int Ndim, int out_half) {
    extern __shared__ __half shh[];
    const uint32_t shb = (uint32_t)__cvta_generic_to_shared(shh);
    const int tid = threadIdx.x, lane = tid & 31, w = tid >> 5;
    const int g = lane >> 2, tig = lane & 3;
    const int wm = w & 1, wn = w >> 1;
    const int cm0 = blockIdx.y * 128, cn0 = blockIdx.x * 128;
    const int nchunk = Kdim >> 5;

    const int ti = lane >> 3, ri = lane & 7;
    const uint32_t offA = (uint32_t)((((ti & 1) * 8 + ri) * AH + (ti >> 1) * 8) * 2);
    const uint32_t offB = (uint32_t)((((ti & 1) * 8 + ri) * BH + (ti >> 1) * 8) * 2);

    auto load = [&](int c, int s) {
        const uint32_t sb = shb + s * (STGH * 2);
#pragma unroll
        for (int i = 0; i < 4; i++) {               // A: 128 rows x 64B
            int seg = i * 128 + tid;
            int row = seg >> 2, ks = seg & 3;
            CP16(sb + (row * AH + ks * 8) * 2,
                 A + (size_t)(cm0 + row) * Kdim + c * 32 + ks * 8);
        }
        const uint32_t bb = sb + 128 * AH * 2;
#pragma unroll
        for (int i = 0; i < 4; i++) {               // B: 32 rows x 256B (dense)
            int seg = i * 128 + tid;
            int row = seg >> 4, ns = seg & 15;
            CP16(bb + (row * BH + ns * 8) * 2,
                 W + (size_t)(c * 32 + row) * Ndim + cn0 + ns * 8);
        }
    };

    float acc[4][8][4];
#pragma unroll
    for (int i = 0; i < 4; i++)
#pragma unroll
        for (int j = 0; j < 8; j++)
#pragma unroll
            for (int r = 0; r < 4; r++) acc[i][j][r] = 0.0f;

    load(0, 0); CP_COMMIT();
    load(1, 1); CP_COMMIT();
    load(2, 2); CP_COMMIT();

    for (int c = 0; c < nchunk; c++) {
        asm volatile("cp.async.wait_group 2;" ::: "memory");
        __syncthreads();
        if (c + 3 < nchunk) load(c + 3, (c + 3) & 3);
        CP_COMMIT();

        const uint32_t aBase = shb + (c & 3) * (STGH * 2);
        const uint32_t bBase = aBase + 128 * AH * 2;
#pragma unroll
        for (int h = 0; h < 2; h++) {
            uint32_t afr[4][4], bfr[8][2];
#pragma unroll
            for (int fm = 0; fm < 4; fm++)
                LDSM4(afr[fm][0], afr[fm][1], afr[fm][2], afr[fm][3],
                      aBase + (uint32_t)((((wm * 64 + fm * 16) * AH) + h * 16) * 2) + offA);
#pragma unroll
            for (int p = 0; p < 4; p++)
                LDSM4T(bfr[2 * p][0], bfr[2 * p][1], bfr[2 * p + 1][0], bfr[2 * p + 1][1],
                       bBase + (uint32_t)(((h * 16) * BH + wn * 64 + p * 16) * 2) + offB);
#pragma unroll
            for (int fm = 0; fm < 4; fm++)
#pragma unroll
                for (int fn = 0; fn < 8; fn++)
                    MMA_F16(acc[fm][fn], afr[fm], bfr[fn]);
        }
    }

    const int m0 = cm0 + wm * 64;
    const int n0 = cn0 + wn * 64;
    if (out_half) {
        __half* Ch = (__half*)Cout;
#pragma unroll
        for (int fm = 0; fm < 4; fm++) {
            int row = m0 + fm * 16 + g;
#pragma unroll
            for (int fn = 0; fn < 8; fn++) {
                int col = n0 + fn * 8 + tig * 2;
                *(uint32_t*)(Ch + (size_t)row * Ndim + col) =
                    packh2(acc[fm][fn][0], acc[fm][fn][1]);
                *(uint32_t*)(Ch + (size_t)(row + 8) * Ndim + col) =
                    packh2(acc[fm][fn][2], acc[fm][fn][3]);
            }
        }
    } else {
        float* Cf = (float*)Cout;
#pragma unroll
        for (int fm = 0; fm < 4; fm++) {
            int row = m0 + fm * 16 + g;
#pragma unroll
            for (int fn = 0; fn < 8; fn++) {
                int col = n0 + fn * 8 + tig * 2;
                float* cp = Cf + (size_t)row * Ndim + col;
                *(float2*)cp = make_float2(acc[fm][fn][0], acc[fm][fn][1]);
                *(float2*)(cp + (size_t)8 * Ndim) = make_float2(acc[fm][fn][2], acc[fm][fn][3]);
            }
        }
    }
}

// ---------------------------------------------------------------------------
// RoPE (NeoX half-split) on fp16 q/k, fp32 math.
// ---------------------------------------------------------------------------
__global__ void rope_kernel(const int* __restrict__ pos) {
    int t = blockIdx.x;
    int head = blockIdx.y;
    int h = threadIdx.x;  // 0..63
    __half* buf;
    if (head < N_Q)
        buf = g_qh + ((size_t)t * N_Q + head) * HD;
    else
        buf = g_kh + ((size_t)t * N_KV + (head - N_Q)) * HD;

    float p = (float)pos[t];
    float f = p * __expf(-((float)h / 64.0f) * 9.210340371976184f);
    float c = cosf(f);
    float s = sinf(f);
    float x1 = __half2float(buf[h]);
    float x2 = __half2float(buf[h + 64]);
    buf[h] = __float2half_rn(x1 * c - x2 * s);
    buf[h + 64] = __float2half_rn(x2 * c + x1 * s);
}

// ---------------------------------------------------------------------------
// Flash attention (fp16 mma.sync m16n8k16), causal GQA.
// CTA: 128 q rows x (head, batch); 8 warps x 16 rows.
// SMEM (halves): Q[128][136], K[64][136], V[64][136], P[128][72].
// Frags: Q,K,P non-trans ldmatrix; V trans ldmatrix. All conflict-free.
// ---------------------------------------------------------------------------
#define QH 136
#define KH 136
#define VH 136
#define PH 72
#define BIG_NEG (-3.0e38f)

__global__ __launch_bounds__(256) void attn_h() {
    extern __shared__ __half smh[];
    __half* Ph = smh + 128 * QH + 64 * KH + 64 * VH;
    const uint32_t smb = (uint32_t)__cvta_generic_to_shared(smh);
    const uint32_t QsB = smb;
    const uint32_t KsB = smb + 128 * QH * 2;
    const uint32_t VsB = KsB + 64 * KH * 2;
    const uint32_t PsB = VsB + 64 * VH * 2;

    const int mt = blockIdx.x, n = blockIdx.y, b = blockIdx.z;
    const int kvh = n >> 2;
    const int tid = threadIdx.x, lane = tid & 31, w = tid >> 5;
    const int g = lane >> 2, tig = lane & 3;
    const int m0 = mt * 128;
    const int wrow = w * 16;
    const int wr_min = m0 + wrow;

    const int ti = lane >> 3, ri = lane & 7;
    const uint32_t offQ = (uint32_t)((((ti & 1) * 8 + ri) * QH + (ti >> 1) * 8) * 2);
    const uint32_t offK = (uint32_t)((((ti & 1) * 8 + ri) * KH + (ti >> 1) * 8) * 2);
    const uint32_t offV = (uint32_t)((((ti & 1) * 8 + ri) * VH + (ti >> 1) * 8) * 2);
    const uint32_t offP = (uint32_t)((((ti & 1) * 8 + ri) * PH + (ti >> 1) * 8) * 2);

    // Q tile: 128 rows x 256B = 2048 segs
#pragma unroll
    for (int i = 0; i < 8; i++) {
        int seg = i * 256 + tid;
        int row = seg >> 4, ks = seg & 15;
        CP16(QsB + (row * QH + ks * 8) * 2,
             g_qh + ((size_t)(b * SEQ + m0 + row) * N_Q + n) * HD + ks * 8);
    }
    CP_COMMIT();

    float m_i0 = BIG_NEG, m_i1 = BIG_NEG;
    float l_i0 = 0.0f, l_i1 = 0.0f;
    float o[16][4];
#pragma unroll
    for (int fn = 0; fn < 16; fn++)
#pragma unroll
        for (int r = 0; r < 4; r++) o[fn][r] = 0.0f;

    const float scale = 0.08838834764831845f;
    const int ntiles = 2 * (mt + 1);

    for (int jt = 0; jt < ntiles; jt++) {
        __syncthreads();
#pragma unroll
        for (int i = 0; i < 4; i++) {
            int seg = i * 256 + tid;
            int row = seg >> 4, ks = seg & 15;
            size_t gof = ((size_t)(b * SEQ + jt * 64 + row) * N_KV + kvh) * HD + ks * 8;
            CP16(KsB + (row * KH + ks * 8) * 2, g_kh + gof);
            CP16(VsB + (row * VH + ks * 8) * 2, g_vh + gof);
        }
        CP_COMMIT();
        asm volatile("cp.async.wait_group 0;" ::: "memory");
        __syncthreads();

        if (jt * 64 <= wr_min + 15) {
            // ---- S = Q K^T (16 x 64) ----
            float s[8][4];
#pragma unroll
            for (int fn = 0; fn < 8; fn++)
#pragma unroll
                for (int r = 0; r < 4; r++) s[fn][r] = 0.0f;

#pragma unroll
            for (int ks = 0; ks < 8; ks++) {
                uint32_t aq[4], bk[8][2];
                LDSM4(aq[0], aq[1], aq[2], aq[3],
                      QsB + (uint32_t)((wrow * QH + ks * 16) * 2) + offQ);
#pragma unroll
                for (int p = 0; p < 4; p++)
                    LDSM4(bk[2 * p][0], bk[2 * p + 1][0], bk[2 * p][1], bk[2 * p + 1][1],
                          KsB + (uint32_t)(((p * 16) * KH + ks * 16) * 2) + offK);
#pragma unroll
                for (int fn = 0; fn < 8; fn++)
                    MMA_F16(s[fn], aq, bk[fn]);
            }

            // ---- softmax on C fragments (fp32) ----
            const int row0 = wr_min + g, row1 = row0 + 8;
            const bool diag = (jt * 64 + 63 > row0);
            float tm0 = BIG_NEG, tm1 = BIG_NEG;
#pragma unroll
            for (int fn = 0; fn < 8; fn++) {
                int colb = jt * 64 + fn * 8 + 2 * tig;
                float v0 = s[fn][0] * scale;
                float v1 = s[fn][1] * scale;
                float v2 = s[fn][2] * scale;
                float v3 = s[fn][3] * scale;
                if (diag) {
                    if (colb > row0) v0 = BIG_NEG;
                    if (colb + 1 > row0) v1 = BIG_NEG;
                    if (colb > row1) v2 = BIG_NEG;
                    if (colb + 1 > row1) v3 = BIG_NEG;
                }
                s[fn][0] = v0; s[fn][1] = v1; s[fn][2] = v2; s[fn][3] = v3;
                tm0 = fmaxf(tm0, fmaxf(v0, v1));
                tm1 = fmaxf(tm1, fmaxf(v2, v3));
            }
            tm0 = fmaxf(tm0, __shfl_xor_sync(0xffffffff, tm0, 1));
            tm0 = fmaxf(tm0, __shfl_xor_sync(0xffffffff, tm0, 2));
            tm1 = fmaxf(tm1, __shfl_xor_sync(0xffffffff, tm1, 1));
            tm1 = fmaxf(tm1, __shfl_xor_sync(0xffffffff, tm1, 2));

            float mn0 = fmaxf(m_i0, tm0), mn1 = fmaxf(m_i1, tm1);
            float corr0 = __expf(m_i0 - mn0), corr1 = __expf(m_i1 - mn1);
            m_i0 = mn0; m_i1 = mn1;

            float ls0 = 0.0f, ls1 = 0.0f;
            __half* pw = Ph + (wrow + g) * PH + 2 * tig;
#pragma unroll
            for (int fn = 0; fn < 8; fn++) {
                float p0 = __expf(s[fn][0] - mn0);
                float p1 = __expf(s[fn][1] - mn0);
                float p2 = __expf(s[fn][2] - mn1);
                float p3 = __expf(s[fn][3] - mn1);
                ls0 += p0 + p1;
                ls1 += p2 + p3;
                *(uint32_t*)(pw + fn * 8) = packh2(p0, p1);
                *(uint32_t*)(pw + 8 * PH + fn * 8) = packh2(p2, p3);
            }
            ls0 += __shfl_xor_sync(0xffffffff, ls0, 1);
            ls0 += __shfl_xor_sync(0xffffffff, ls0, 2);
            ls1 += __shfl_xor_sync(0xffffffff, ls1, 1);
            ls1 += __shfl_xor_sync(0xffffffff, ls1, 2);
            l_i0 = l_i0 * corr0 + ls0;
            l_i1 = l_i1 * corr1 + ls1;

#pragma unroll
            for (int fn = 0; fn < 16; fn++) {
                o[fn][0] *= corr0; o[fn][1] *= corr0;
                o[fn][2] *= corr1; o[fn][3] *= corr1;
            }

            __syncwarp();  // P visible warp-wide

            // ---- O += P V (16 x 128) ----
#pragma unroll
            for (int ks = 0; ks < 4; ks++) {
                uint32_t ap[4], bv[16][2];
                LDSM4(ap[0], ap[1], ap[2], ap[3],
                      PsB + (uint32_t)((wrow * PH + ks * 16) * 2) + offP);
#pragma unroll
                for (int p = 0; p < 8; p++)
                    LDSM4T(bv[2 * p][0], bv[2 * p][1], bv[2 * p + 1][0], bv[2 * p + 1][1],
                           VsB + (uint32_t)(((ks * 16) * VH + p * 16) * 2) + offV);
#pragma unroll
                for (int fn = 0; fn < 16; fn++)
                    MMA_F16(o[fn], ap, bv[fn]);
            }
            __syncwarp();
        }
    }

    // epilogue: fp16 out (O-proj consumes half)
    float inv0 = 1.0f / l_i0, inv1 = 1.0f / l_i1;
    __half* op0 = g_atth + ((size_t)(b * SEQ + wr_min + g) * N_Q + n) * HD;
    __half* op1 = op0 + (size_t)8 * N_Q * HD;
#pragma unroll
    for (int fn = 0; fn < 16; fn++) {
        int col = fn * 8 + 2 * tig;
        *(uint32_t*)(op0 + col) = packh2(o[fn][0] * inv0, o[fn][1] * inv0);
        *(uint32_t*)(op1 + col) = packh2(o[fn][2] * inv1, o[fn][3] * inv1);
    }
}

// ---------------------------------------------------------------------------
// Launch
// ---------------------------------------------------------------------------
extern "C" void kernel_launch(void* const* d_in, const int* in_sizes, int n_in,
                              void* d_out, int out_size) {
    const float* x  = (const float*)d_in[0];
    const int* pos  = (const int*)d_in[1];
    const float* Wq = (const float*)d_in[2];
    const float* Wk = (const float*)d_in[3];
    const float* Wv = (const float*)d_in[4];
    const float* Wo = (const float*)d_in[5];
    float* out = (float*)d_out;
    (void)in_sizes; (void)n_in; (void)out_size;

    __half *xh, *wqh, *wkh, *wvh, *woh, *qh, *kh, *vh, *ath;
    cudaGetSymbolAddress((void**)&xh, g_xh);
    cudaGetSymbolAddress((void**)&wqh, g_wqh);
    cudaGetSymbolAddress((void**)&wkh, g_wkh);
    cudaGetSymbolAddress((void**)&wvh, g_wvh);
    cudaGetSymbolAddress((void**)&woh, g_woh);
    cudaGetSymbolAddress((void**)&qh, g_qh);
    cudaGetSymbolAddress((void**)&kh, g_kh);
    cudaGetSymbolAddress((void**)&vh, g_vh);
    cudaGetSymbolAddress((void**)&ath, g_atth);

    // fp32 -> fp16 conversions
    conv_h<<<T_TOK * D_MODEL / 2048, 256>>>(x, xh, T_TOK * D_MODEL / 8);
    conv_h<<<D_MODEL * N_Q * HD / 2048, 256>>>(Wq, wqh, D_MODEL * N_Q * HD / 8);
    conv_h<<<D_MODEL * N_KV * HD / 2048, 256>>>(Wk, wkh, D_MODEL * N_KV * HD / 8);
    conv_h<<<D_MODEL * N_KV * HD / 2048, 256>>>(Wv, wvh, D_MODEL * N_KV * HD / 8);
    conv_h<<<N_Q * HD * D_MODEL / 2048, 256>>>(Wo, woh, N_Q * HD * D_MODEL / 8);

    const int gemm_smem = 4 * STGH * 2;  // 75776 B
    cudaFuncSetAttribute(gemm_h, cudaFuncAttributeMaxDynamicSharedMemorySize, gemm_smem);

    // QKV projections (fp16 out)
    gemm_h<<<dim3(32, 32), 128, gemm_smem>>>(xh, wqh, qh, D_MODEL, N_Q * HD, 1);
    gemm_h<<<dim3(8, 32), 128, gemm_smem>>>(xh, wkh, kh, D_MODEL, N_KV * HD, 1);
    gemm_h<<<dim3(8, 32), 128, gemm_smem>>>(xh, wvh, vh, D_MODEL, N_KV * HD, 1);

    // RoPE on fp16 q/k
    rope_kernel<<<dim3(T_TOK, N_Q + N_KV), 64>>>(pos);

    // Flash attention (fp16 tensor cores)
    const int attn_smem = (128 * QH + 64 * KH + 64 * VH + 128 * PH) * 2;  // 88064 B
    cudaFuncSetAttribute(attn_h, cudaFuncAttributeMaxDynamicSharedMemorySize, attn_smem);
    attn_h<<<dim3(SEQ / 128, N_Q, BATCH), 256, attn_smem>>>();

    // Output projection (fp32 out)
    gemm_h<<<dim3(32, 32), 128, gemm_smem>>>(ath, woh, out, D_MODEL, D_MODEL, 0);
}

// round 15
// speedup vs baseline: 2.9200x; 1.0572x over previous
#include <cuda_runtime.h>
#include <cuda_fp16.h>
#include <cstdint>
#include <math.h>

// Problem constants (Llama-3-8B-like prefill)
#define T_TOK 4096
#define D_MODEL 4096
#define N_Q 32
#define N_KV 8
#define HD 128
#define SEQ 1024
#define BATCH 4
#define NQKV 6144   // N_Q*HD + 2*N_KV*HD

// Scratch (allocation-free rule: __device__ globals), all fp16
__device__ __half g_xh[T_TOK * D_MODEL];
__device__ __half g_wqkvh[D_MODEL * NQKV];      // [D][ wq(4096) | wk(1024) | wv(1024) ]
__device__ __half g_woh[N_Q * HD * D_MODEL];
__device__ __half g_qh[T_TOK * N_Q * HD];
__device__ __half g_kh[T_TOK * N_KV * HD];
__device__ __half g_vh[T_TOK * N_KV * HD];
__device__ __half g_atth[T_TOK * N_Q * HD];

__device__ __forceinline__ uint32_t packh2(float a, float b) {
    __half2 h = __floats2half2_rn(a, b);
    return *(uint32_t*)&h;
}

#define MMA_F16(d, a, b)                                                      \
    asm volatile(                                                             \
        "mma.sync.aligned.m16n8k16.row.col.f32.f16.f16.f32 "                  \
        "{%0,%1,%2,%3}, {%4,%5,%6,%7}, {%8,%9}, {%0,%1,%2,%3};"               \
        : "+f"((d)[0]), "+f"((d)[1]), "+f"((d)[2]), "+f"((d)[3])              \
        : "r"((a)[0]), "r"((a)[1]), "r"((a)[2]), "r"((a)[3]),                 \
          "r"((b)[0]), "r"((b)[1]))

#define CP16(dst, src) \
    asm volatile("cp.async.cg.shared.global [%0], [%1], 16;" :: "r"(dst), "l"(src))
#define CP_COMMIT() asm volatile("cp.async.commit_group;" ::: "memory")

#define LDSM4(r0, r1, r2, r3, addr)                                           \
    asm volatile("ldmatrix.sync.aligned.m8n8.x4.shared.b16 {%0,%1,%2,%3}, [%4];" \
        : "=r"(r0), "=r"(r1), "=r"(r2), "=r"(r3) : "r"(addr))
#define LDSM4T(r0, r1, r2, r3, addr)                                          \
    asm volatile("ldmatrix.sync.aligned.m8n8.x4.trans.shared.b16 {%0,%1,%2,%3}, [%4];" \
        : "=r"(r0), "=r"(r1), "=r"(r2), "=r"(r3) : "r"(addr))

// ---------------------------------------------------------------------------
// fp32 -> fp16 conversion, contiguous, 8 elems/thread
// ---------------------------------------------------------------------------
__global__ void conv_h(const float* __restrict__ in, __half* __restrict__ out, int n8) {
    int i = blockIdx.x * 256 + threadIdx.x;
    if (i < n8) {
        float4 a = ((const float4*)in)[2 * i];
        float4 b = ((const float4*)in)[2 * i + 1];
        ((uint4*)out)[i] = make_uint4(packh2(a.x, a.y), packh2(a.z, a.w),
                                      packh2(b.x, b.y), packh2(b.z, b.w));
    }
}

// ---------------------------------------------------------------------------
// fp32 [R][C] -> fp16 segment of concatenated weights: out row stride OS,
// column offset CO. 8 elems/thread; C multiple of 8.
// ---------------------------------------------------------------------------
__global__ void conv_seg(const float* __restrict__ in, __half* __restrict__ out,
                         int C, int OS, int CO, int n8) {
    int i = blockIdx.x * 256 + threadIdx.x;
    if (i < n8) {
        int e = i * 8;
        int r = e / C, c = e % C;
        float4 a = ((const float4*)in)[2 * i];
        float4 b = ((const float4*)in)[2 * i + 1];
        uint4 o = make_uint4(packh2(a.x, a.y), packh2(a.z, a.w),
                             packh2(b.x, b.y), packh2(b.z, b.w));
        *(uint4*)(out + (size_t)r * OS + CO + c) = o;
    }
}

// ---------------------------------------------------------------------------
// FP16 mma.sync GEMM: C[M,N] = A[M,K] @ W[K,N].
// 128x128 CTA tile, BK=32, 128 thr, 4 warps (2x2), warp tile 64x64.
// All fragments via ldmatrix (A non-trans; W trans from dense [k][n]).
// 4-stage cp.async, 1 barrier/chunk. (verified R12)
// out_half==1: epilogue routes 128-col tiles to q/k/v by column segment.
// out_half==0: fp32 out to Cout.
// ---------------------------------------------------------------------------
#define AH 40
#define BH 136
#define STGH (128 * AH + 32 * BH)   // 9472 halves
__global__ __launch_bounds__(128, 2) void gemm_h(const __half* __restrict__ A,
                                                 const __half* __restrict__ W,
                                                 void* __restrict__ Cout,
                                                 int Kdim, int Ndim, int out_half) {
    extern __shared__ __half shh[];
    const uint32_t shb = (uint32_t)__cvta_generic_to_shared(shh);
    const int tid = threadIdx.x, lane = tid & 31, w = tid >> 5;
    const int g = lane >> 2, tig = lane & 3;
    const int wm = w & 1, wn = w >> 1;
    const int cm0 = blockIdx.y * 128, cn0 = blockIdx.x * 128;
    const int nchunk = Kdim >> 5;

    const int ti = lane >> 3, ri = lane & 7;
    const uint32_t offA = (uint32_t)((((ti & 1) * 8 + ri) * AH + (ti >> 1) * 8) * 2);
    const uint32_t offB = (uint32_t)((((ti & 1) * 8 + ri) * BH + (ti >> 1) * 8) * 2);

    auto load = [&](int c, int s) {
        const uint32_t sb = shb + s * (STGH * 2);
#pragma unroll
        for (int i = 0; i < 4; i++) {
            int seg = i * 128 + tid;
            int row = seg >> 2, ks = seg & 3;
            CP16(sb + (row * AH + ks * 8) * 2,
                 A + (size_t)(cm0 + row) * Kdim + c * 32 + ks * 8);
        }
        const uint32_t bb = sb + 128 * AH * 2;
#pragma unroll
        for (int i = 0; i < 4; i++) {
            int seg = i * 128 + tid;
            int row = seg >> 4, ns = seg & 15;
            CP16(bb + (row * BH + ns * 8) * 2,
                 W + (size_t)(c * 32 + row) * Ndim + cn0 + ns * 8);
        }
    };

    float acc[4][8][4];
#pragma unroll
    for (int i = 0; i < 4; i++)
#pragma unroll
        for (int j = 0; j < 8; j++)
#pragma unroll
            for (int r = 0; r < 4; r++) acc[i][j][r] = 0.0f;

    load(0, 0); CP_COMMIT();
    load(1, 1); CP_COMMIT();
    load(2, 2); CP_COMMIT();

    for (int c = 0; c < nchunk; c++) {
        asm volatile("cp.async.wait_group 2;" ::: "memory");
        __syncthreads();
        if (c + 3 < nchunk) load(c + 3, (c + 3) & 3);
        CP_COMMIT();

        const uint32_t aBase = shb + (c & 3) * (STGH * 2);
        const uint32_t bBase = aBase + 128 * AH * 2;
#pragma unroll
        for (int h = 0; h < 2; h++) {
            uint32_t afr[4][4], bfr[8][2];
#pragma unroll
            for (int fm = 0; fm < 4; fm++)
                LDSM4(afr[fm][0], afr[fm][1], afr[fm][2], afr[fm][3],
                      aBase + (uint32_t)((((wm * 64 + fm * 16) * AH) + h * 16) * 2) + offA);
#pragma unroll
            for (int p = 0; p < 4; p++)
                LDSM4T(bfr[2 * p][0], bfr[2 * p][1], bfr[2 * p + 1][0], bfr[2 * p + 1][1],
                       bBase + (uint32_t)(((h * 16) * BH + wn * 64 + p * 16) * 2) + offB);
#pragma unroll
            for (int fm = 0; fm < 4; fm++)
#pragma unroll
                for (int fn = 0; fn < 8; fn++)
                    MMA_F16(acc[fm][fn], afr[fm], bfr[fn]);
        }
    }

    const int m0 = cm0 + wm * 64;
    const int n0 = cn0 + wn * 64;
    if (out_half) {
        // Route by column segment (CTA tile never straddles: 4096/5120 are
        // multiples of 128).
        __half* base;
        int stride, coff;
        if (cn0 < N_Q * HD)                  { base = g_qh; stride = N_Q * HD;  coff = 0; }
        else if (cn0 < N_Q * HD + N_KV * HD) { base = g_kh; stride = N_KV * HD; coff = N_Q * HD; }
        else                                 { base = g_vh; stride = N_KV * HD; coff = N_Q * HD + N_KV * HD; }
#pragma unroll
        for (int fm = 0; fm < 4; fm++) {
            int row = m0 + fm * 16 + g;
#pragma unroll
            for (int fn = 0; fn < 8; fn++) {
                int col = n0 + fn * 8 + tig * 2 - coff;
                *(uint32_t*)(base + (size_t)row * stride + col) =
                    packh2(acc[fm][fn][0], acc[fm][fn][1]);
                *(uint32_t*)(base + (size_t)(row + 8) * stride + col) =
                    packh2(acc[fm][fn][2], acc[fm][fn][3]);
            }
        }
    } else {
        float* Cf = (float*)Cout;
#pragma unroll
        for (int fm = 0; fm < 4; fm++) {
            int row = m0 + fm * 16 + g;
#pragma unroll
            for (int fn = 0; fn < 8; fn++) {
                int col = n0 + fn * 8 + tig * 2;
                float* cp = Cf + (size_t)row * Ndim + col;
                *(float2*)cp = make_float2(acc[fm][fn][0], acc[fm][fn][1]);
                *(float2*)(cp + (size_t)8 * Ndim) = make_float2(acc[fm][fn][2], acc[fm][fn][3]);
            }
        }
    }
}

// ---------------------------------------------------------------------------
// RoPE (NeoX half-split), fp32 math on fp16 data. One block per token.
// cos/sin computed once into smem; 40 heads x 64 pairs grid-strided.
// ---------------------------------------------------------------------------
__global__ __launch_bounds__(256) void rope_kernel(const int* __restrict__ pos) {
    __shared__ float cs[64], sn[64];
    const int t = blockIdx.x;
    const int tid = threadIdx.x;
    if (tid < 64) {
        float p = (float)pos[t];
        float f = p * __expf(-((float)tid / 64.0f) * 9.210340371976184f);
        cs[tid] = cosf(f);
        sn[tid] = sinf(f);
    }
    __syncthreads();
    __half* qb = g_qh + (size_t)t * N_Q * HD;
    __half* kb = g_kh + (size_t)t * N_KV * HD;
#pragma unroll
    for (int it = tid; it < (N_Q + N_KV) * 64; it += 256) {
        int head = it >> 6, h = it & 63;
        __half* buf = (head < N_Q) ? (qb + head * HD) : (kb + (head - N_Q) * HD);
        float c = cs[h], s = sn[h];
        float x1 = __half2float(buf[h]);
        float x2 = __half2float(buf[h + 64]);
        buf[h] = __float2half_rn(x1 * c - x2 * s);
        buf[h + 64] = __float2half_rn(x2 * c + x1 * s);
    }
}

// ---------------------------------------------------------------------------
// Flash attention (fp16 mma.sync m16n8k16), causal GQA. (verified R12)
// ---------------------------------------------------------------------------
#define QH 136
#define KH 136
#define VH 136
#define PH 72
#define BIG_NEG (-3.0e38f)

__global__ __launch_bounds__(256) void attn_h() {
    extern __shared__ __half smh[];
    __half* Ph = smh + 128 * QH + 64 * KH + 64 * VH;
    const uint32_t smb = (uint32_t)__cvta_generic_to_shared(smh);
    const uint32_t QsB = smb;
    const uint32_t KsB = smb + 128 * QH * 2;
    const uint32_t VsB = KsB + 64 * KH * 2;
    const uint32_t PsB = VsB + 64 * VH * 2;

    const int mt = blockIdx.x, n = blockIdx.y, b = blockIdx.z;
    const int kvh = n >> 2;
    const int tid = threadIdx.x, lane = tid & 31, w = tid >> 5;
    const int g = lane >> 2, tig = lane & 3;
    const int m0 = mt * 128;
    const int wrow = w * 16;
    const int wr_min = m0 + wrow;

    const int ti = lane >> 3, ri = lane & 7;
    const uint32_t offQ = (uint32_t)((((ti & 1) * 8 + ri) * QH + (ti >> 1) * 8) * 2);
    const uint32_t offK = (uint32_t)((((ti & 1) * 8 + ri) * KH + (ti >> 1) * 8) * 2);
    const uint32_t offV = (uint32_t)((((ti & 1) * 8 + ri) * VH + (ti >> 1) * 8) * 2);
    const uint32_t offP = (uint32_t)((((ti & 1) * 8 + ri) * PH + (ti >> 1) * 8) * 2);

#pragma unroll
    for (int i = 0; i < 8; i++) {
        int seg = i * 256 + tid;
        int row = seg >> 4, ks = seg & 15;
        CP16(QsB + (row * QH + ks * 8) * 2,
             g_qh + ((size_t)(b * SEQ + m0 + row) * N_Q + n) * HD + ks * 8);
    }
    CP_COMMIT();

    float m_i0 = BIG_NEG, m_i1 = BIG_NEG;
    float l_i0 = 0.0f, l_i1 = 0.0f;
    float o[16][4];
#pragma unroll
    for (int fn = 0; fn < 16; fn++)
#pragma unroll
        for (int r = 0; r < 4; r++) o[fn][r] = 0.0f;

    const float scale = 0.08838834764831845f;
    const int ntiles = 2 * (mt + 1);

    for (int jt = 0; jt < ntiles; jt++) {
        __syncthreads();
#pragma unroll
        for (int i = 0; i < 4; i++) {
            int seg = i * 256 + tid;
            int row = seg >> 4, ks = seg & 15;
            size_t gof = ((size_t)(b * SEQ + jt * 64 + row) * N_KV + kvh) * HD + ks * 8;
            CP16(KsB + (row * KH + ks * 8) * 2, g_kh + gof);
            CP16(VsB + (row * VH + ks * 8) * 2, g_vh + gof);
        }
        CP_COMMIT();
        asm volatile("cp.async.wait_group 0;" ::: "memory");
        __syncthreads();

        if (jt * 64 <= wr_min + 15) {
            float s[8][4];
#pragma unroll
            for (int fn = 0; fn < 8; fn++)
#pragma unroll
                for (int r = 0; r < 4; r++) s[fn][r] = 0.0f;

#pragma unroll
            for (int ks = 0; ks < 8; ks++) {
                uint32_t aq[4], bk[8][2];
                LDSM4(aq[0], aq[1], aq[2], aq[3],
                      QsB + (uint32_t)((wrow * QH + ks * 16) * 2) + offQ);
#pragma unroll
                for (int p = 0; p < 4; p++)
                    LDSM4(bk[2 * p][0], bk[2 * p + 1][0], bk[2 * p][1], bk[2 * p + 1][1],
                          KsB + (uint32_t)(((p * 16) * KH + ks * 16) * 2) + offK);
#pragma unroll
                for (int fn = 0; fn < 8; fn++)
                    MMA_F16(s[fn], aq, bk[fn]);
            }

            const int row0 = wr_min + g, row1 = row0 + 8;
            const bool diag = (jt * 64 + 63 > row0);
            float tm0 = BIG_NEG, tm1 = BIG_NEG;
#pragma unroll
            for (int fn = 0; fn < 8; fn++) {
                int colb = jt * 64 + fn * 8 + 2 * tig;
                float v0 = s[fn][0] * scale;
                float v1 = s[fn][1] * scale;
                float v2 = s[fn][2] * scale;
                float v3 = s[fn][3] * scale;
                if (diag) {
                    if (colb > row0) v0 = BIG_NEG;
                    if (colb + 1 > row0) v1 = BIG_NEG;
                    if (colb > row1) v2 = BIG_NEG;
                    if (colb + 1 > row1) v3 = BIG_NEG;
                }
                s[fn][0] = v0; s[fn][1] = v1; s[fn][2] = v2; s[fn][3] = v3;
                tm0 = fmaxf(tm0, fmaxf(v0, v1));
                tm1 = fmaxf(tm1, fmaxf(v2, v3));
            }
            tm0 = fmaxf(tm0, __shfl_xor_sync(0xffffffff, tm0, 1));
            tm0 = fmaxf(tm0, __shfl_xor_sync(0xffffffff, tm0, 2));
            tm1 = fmaxf(tm1, __shfl_xor_sync(0xffffffff, tm1, 1));
            tm1 = fmaxf(tm1, __shfl_xor_sync(0xffffffff, tm1, 2));

            float mn0 = fmaxf(m_i0, tm0), mn1 = fmaxf(m_i1, tm1);
            float corr0 = __expf(m_i0 - mn0), corr1 = __expf(m_i1 - mn1);
            m_i0 = mn0; m_i1 = mn1;

            float ls0 = 0.0f, ls1 = 0.0f;
            __half* pw = Ph + (wrow + g) * PH + 2 * tig;
#pragma unroll
            for (int fn = 0; fn < 8; fn++) {
                float p0 = __expf(s[fn][0] - mn0);
                float p1 = __expf(s[fn][1] - mn0);
                float p2 = __expf(s[fn][2] - mn1);
                float p3 = __expf(s[fn][3] - mn1);
                ls0 += p0 + p1;
                ls1 += p2 + p3;
                *(uint32_t*)(pw + fn * 8) = packh2(p0, p1);
                *(uint32_t*)(pw + 8 * PH + fn * 8) = packh2(p2, p3);
            }
            ls0 += __shfl_xor_sync(0xffffffff, ls0, 1);
            ls0 += __shfl_xor_sync(0xffffffff, ls0, 2);
            ls1 += __shfl_xor_sync(0xffffffff, ls1, 1);
            ls1 += __shfl_xor_sync(0xffffffff, ls1, 2);
            l_i0 = l_i0 * corr0 + ls0;
            l_i1 = l_i1 * corr1 + ls1;

#pragma unroll
            for (int fn = 0; fn < 16; fn++) {
                o[fn][0] *= corr0; o[fn][1] *= corr0;
                o[fn][2] *= corr1; o[fn][3] *= corr1;
            }

            __syncwarp();

#pragma unroll
            for (int ks = 0; ks < 4; ks++) {
                uint32_t ap[4], bv[16][2];
                LDSM4(ap[0], ap[1], ap[2], ap[3],
                      PsB + (uint32_t)((wrow * PH + ks * 16) * 2) + offP);
#pragma unroll
                for (int p = 0; p < 8; p++)
                    LDSM4T(bv[2 * p][0], bv[2 * p][1], bv[2 * p + 1][0], bv[2 * p + 1][1],
                           VsB + (uint32_t)(((ks * 16) * VH + p * 16) * 2) + offV);
#pragma unroll
                for (int fn = 0; fn < 16; fn++)
                    MMA_F16(o[fn], ap, bv[fn]);
            }
            __syncwarp();
        }
    }

    float inv0 = 1.0f / l_i0, inv1 = 1.0f / l_i1;
    __half* op0 = g_atth + ((size_t)(b * SEQ + wr_min + g) * N_Q + n) * HD;
    __half* op1 = op0 + (size_t)8 * N_Q * HD;
#pragma unroll
    for (int fn = 0; fn < 16; fn++) {
        int col = fn * 8 + 2 * tig;
        *(uint32_t*)(op0 + col) = packh2(o[fn][0] * inv0, o[fn][1] * inv0);
        *(uint32_t*)(op1 + col) = packh2(o[fn][2] * inv1, o[fn][3] * inv1);
    }
}

// ---------------------------------------------------------------------------
// Launch
// ---------------------------------------------------------------------------
extern "C" void kernel_launch(void* const* d_in, const int* in_sizes, int n_in,
                              void* d_out, int out_size) {
    const float* x  = (const float*)d_in[0];
    const int* pos  = (const int*)d_in[1];
    const float* Wq = (const float*)d_in[2];
    const float* Wk = (const float*)d_in[3];
    const float* Wv = (const float*)d_in[4];
    const float* Wo = (const float*)d_in[5];
    float* out = (float*)d_out;
    (void)in_sizes; (void)n_in; (void)out_size;

    __half *xh, *wqkvh, *woh, *ath;
    cudaGetSymbolAddress((void**)&xh, g_xh);
    cudaGetSymbolAddress((void**)&wqkvh, g_wqkvh);
    cudaGetSymbolAddress((void**)&woh, g_woh);
    cudaGetSymbolAddress((void**)&ath, g_atth);

    // fp32 -> fp16 conversions (weights concatenated per-row into g_wqkvh)
    conv_h<<<T_TOK * D_MODEL / 2048, 256>>>(x, xh, T_TOK * D_MODEL / 8);
    conv_seg<<<D_MODEL * N_Q * HD / 2048, 256>>>(Wq, wqkvh, N_Q * HD, NQKV, 0,
                                                 D_MODEL * N_Q * HD / 8);
    conv_seg<<<D_MODEL * N_KV * HD / 2048, 256>>>(Wk, wqkvh, N_KV * HD, NQKV, N_Q * HD,
                                                  D_MODEL * N_KV * HD / 8);
    conv_seg<<<D_MODEL * N_KV * HD / 2048, 256>>>(Wv, wqkvh, N_KV * HD, NQKV,
                                                  N_Q * HD + N_KV * HD,
                                                  D_MODEL * N_KV * HD / 8);
    conv_h<<<N_Q * HD * D_MODEL / 2048, 256>>>(Wo, woh, N_Q * HD * D_MODEL / 8);

    const int gemm_smem = 4 * STGH * 2;  // 75776 B
    cudaFuncSetAttribute(gemm_h, cudaFuncAttributeMaxDynamicSharedMemorySize, gemm_smem);

    // Fused QKV projection (one launch, epilogue routes q/k/v)
    gemm_h<<<dim3(NQKV / 128, 32), 128, gemm_smem>>>(xh, wqkvh, nullptr,
                                                     D_MODEL, NQKV, 1);

    // RoPE on fp16 q/k (one block per token)
    rope_kernel<<<T_TOK, 256>>>(pos);

    // Flash attention (fp16 tensor cores)
    const int attn_smem = (128 * QH + 64 * KH + 64 * VH + 128 * PH) * 2;  // 88064 B
    cudaFuncSetAttribute(attn_h, cudaFuncAttributeMaxDynamicSharedMemorySize, attn_smem);
    attn_h<<<dim3(SEQ / 128, N_Q, BATCH), 256, attn_smem>>>();

    // Output projection (fp32 out)
    gemm_h<<<dim3(32, 32), 128, gemm_smem>>>(ath, woh, out, D_MODEL, D_MODEL, 0);
}